// round 10
// baseline (speedup 1.0000x reference)
#include <cuda_runtime.h>
#include <cuda_fp16.h>
#include <cstdint>

// Problem dims
#define T_DIM 256
#define B_DIM 128
#define I_DIM 512
#define H_DIM 2048
#define O_DIM 512
#define M_DIM (T_DIM * B_DIM)      // 32768
#define BH    (B_DIM * H_DIM)      // 262144

// Scratch (device globals: no allocation allowed)
__device__ static __half g_A2[(size_t)M_DIM * I_DIM];    // 32 MB fp16 X
__device__ static __half g_B2[(size_t)H_DIM * I_DIM];    // 2 MB  fp16 W_IH
__device__ static __half g_proj[(size_t)M_DIM * H_DIM];  // 128 MB fp16 proj
__device__ static float g_hfinal[BH];                    // 1 MB
__device__ static float g_part[4 * B_DIM * O_DIM];       // 1 MB (gemm2 split-K)

// ---------------------------------------------------------------------------
__device__ __forceinline__ uint32_t smem_u32(const void* p) {
    uint32_t a;
    asm("{ .reg .u64 t; cvta.to.shared.u64 t, %1; cvt.u32.u64 %0, t; }"
        : "=r"(a) : "l"(p));
    return a;
}

__device__ __forceinline__ void cp16(uint32_t dst, const void* src) {
    asm volatile("cp.async.cg.shared.global [%0], [%1], 16;" :: "r"(dst), "l"(src));
}
#define CP_COMMIT() asm volatile("cp.async.commit_group;" ::: "memory")
#define CP_WAIT(n)  asm volatile("cp.async.wait_group %0;" :: "n"(n) : "memory")

#define LDSM_X4(r0, r1, r2, r3, addr) \
    asm volatile("ldmatrix.sync.aligned.m8n8.x4.shared.b16 {%0,%1,%2,%3}, [%4];" \
                 : "=r"(r0), "=r"(r1), "=r"(r2), "=r"(r3) : "r"(addr))

#define MMA_FP16(d, a, b0, b1) \
    asm volatile("mma.sync.aligned.m16n8k16.row.col.f32.f16.f16.f32 " \
                 "{%0,%1,%2,%3}, {%4,%5,%6,%7}, {%8,%9}, {%0,%1,%2,%3};" \
                 : "+f"((d)[0]), "+f"((d)[1]), "+f"((d)[2]), "+f"((d)[3]) \
                 : "r"((a)[0]), "r"((a)[1]), "r"((a)[2]), "r"((a)[3]), \
                   "r"(b0), "r"(b1))

// ---------------------------------------------------------------------------
// Convert kernels: fp32 -> fp16
// ---------------------------------------------------------------------------
__global__ __launch_bounds__(256)
void convA_kernel(const float* __restrict__ src) {
    int i = blockIdx.x * 256 + threadIdx.x;
    float4 v = ((const float4*)src)[i];
    unsigned short hu[4];
    float f[4] = {v.x, v.y, v.z, v.w};
#pragma unroll
    for (int k = 0; k < 4; k++)
        hu[k] = __half_as_ushort(__float2half(f[k]));
    *(ushort4*)((unsigned short*)g_A2 + (size_t)i * 4) =
        make_ushort4(hu[0], hu[1], hu[2], hu[3]);
}

__global__ __launch_bounds__(256)
void convB_kernel(const float* __restrict__ src) {
    int i = blockIdx.x * 256 + threadIdx.x;
    float4 v = ((const float4*)src)[i];
    unsigned short hu[4];
    float f[4] = {v.x, v.y, v.z, v.w};
#pragma unroll
    for (int k = 0; k < 4; k++)
        hu[k] = __half_as_ushort(__float2half(f[k]));
    *(ushort4*)((unsigned short*)g_B2 + (size_t)i * 4) =
        make_ushort4(hu[0], hu[1], hu[2], hu[3]);
}

// ---------------------------------------------------------------------------
// GEMM1: proj[M, H] = A · B^T over K = 512 (fp16 mma.sync m16n8k16).
// CTA 256x128, 512 threads (16 warps, 4m x 4n of 64x32 warp tiles),
// 1 CTA/SM -> same 16 warps/SM as best config but 33% less L2 traffic.
// NS=3 cp.async pipeline, ONE barrier per chunk (bottom barrier is
// redundant: stage written at iter j = (j+2)%3 != stage read = j%3).
// ---------------------------------------------------------------------------
#define NS        3
#define NIT       8
#define A_TILE_B  32768            // 256 rows x 128B
#define B_TILE_B  16384            // 128 rows x 128B
#define STAGE_B   (A_TILE_B + B_TILE_B)   // 49152
#define SMEM_DYN  (NS * STAGE_B)          // 147456

__global__ __launch_bounds__(512, 1)
void gemm1_mma() {
    extern __shared__ char dsm[];
    const uint32_t smem = smem_u32(dsm);

    const int tid  = threadIdx.x;
    const int lane = tid & 31;
    const int wid  = tid >> 5;         // 0..15
    const int wm   = wid & 3;          // m offset: 0/64/128/192
    const int wn   = wid >> 2;         // n offset: 0/32/64/96
    const int bm   = blockIdx.y * 256;
    const int bn   = blockIdx.x * 128;

    // ldmatrix lane geometry
    const int ra = (lane & 7) + ((lane >> 3) & 1) * 8;   // A row-in-tile
    const int ca = lane >> 4;                            // A c16 parity
    const int rb = (lane & 7) + (lane >> 4) * 8;         // B row-in-pairtile
    const int cb = (lane >> 3) & 1;                      // B c16 parity
    const int xr = lane & 7;                             // swizzle key

    float acc[4][4][4];
#pragma unroll
    for (int i = 0; i < 4; i++)
#pragma unroll
        for (int j = 0; j < 4; j++)
#pragma unroll
            for (int k = 0; k < 4; k++) acc[i][j][k] = 0.f;

    auto load_chunk = [&](int lt, int ls) {
        const char* Ab = (const char*)(g_A2 + (size_t)bm * I_DIM + lt * 64);
        const char* Bb = (const char*)(g_B2 + (size_t)bn * I_DIM + lt * 64);
        uint32_t sA = smem + ls * STAGE_B;
        uint32_t sB = sA + A_TILE_B;
#pragma unroll
        for (int i = 0; i < 4; i++) {              // A: 256 rows x 8 x 16B
            int idx = tid + i * 512;               // 0..2047
            int r = idx >> 3, c = idx & 7;
            uint32_t sw = r * 128 + ((c ^ (r & 7)) * 16);
            cp16(sA + sw, Ab + (size_t)r * 1024 + c * 16);
        }
#pragma unroll
        for (int i = 0; i < 2; i++) {              // B: 128 rows x 8 x 16B
            int idx = tid + i * 512;               // 0..1023
            int r = idx >> 3, c = idx & 7;
            uint32_t sw = r * 128 + ((c ^ (r & 7)) * 16);
            cp16(sB + sw, Bb + (size_t)r * 1024 + c * 16);
        }
    };

    load_chunk(0, 0); CP_COMMIT();
    load_chunk(1, 1); CP_COMMIT();

    const uint32_t aRow = (uint32_t)(wm * 64 + ra) * 128;
    const uint32_t bRow = (uint32_t)(wn * 32 + rb) * 128;

    for (int j = 0; j < NIT; j++) {
        CP_WAIT(1);
        __syncthreads();               // single barrier per chunk

        int nxt = j + 2;
        if (nxt < NIT) load_chunk(nxt, nxt % NS);
        CP_COMMIT();

        const uint32_t aB = smem + (j % NS) * STAGE_B;
        const uint32_t bB = aB + A_TILE_B;

#pragma unroll
        for (int ks = 0; ks < 4; ks++) {
            uint32_t a[4][4], b[2][4];
#pragma unroll
            for (int mt = 0; mt < 4; mt++) {
                uint32_t addr = aB + aRow + mt * 16 * 128 +
                                (((ks * 2 + ca) ^ xr) * 16);
                LDSM_X4(a[mt][0], a[mt][1], a[mt][2], a[mt][3], addr);
            }
#pragma unroll
            for (int np = 0; np < 2; np++) {
                uint32_t addr = bB + bRow + np * 16 * 128 +
                                (((ks * 2 + cb) ^ xr) * 16);
                LDSM_X4(b[np][0], b[np][1], b[np][2], b[np][3], addr);
            }
#pragma unroll
            for (int mt = 0; mt < 4; mt++)
#pragma unroll
                for (int nt = 0; nt < 4; nt++)
                    MMA_FP16(acc[mt][nt], a[mt],
                             b[nt >> 1][(nt & 1) * 2], b[nt >> 1][(nt & 1) * 2 + 1]);
        }
    }

    // epilogue: convert to fp16, half2 stores
    const int gq = lane >> 2;
    const int tq = lane & 3;
#pragma unroll
    for (int mt = 0; mt < 4; mt++) {
#pragma unroll
        for (int nt = 0; nt < 4; nt++) {
            int row = bm + wm * 64 + mt * 16 + gq;
            int col = bn + wn * 32 + nt * 8 + tq * 2;
            __half2 v0 = __floats2half2_rn(acc[mt][nt][0], acc[mt][nt][1]);
            __half2 v1 = __floats2half2_rn(acc[mt][nt][2], acc[mt][nt][3]);
            *(__half2*)(g_proj + (size_t)row * H_DIM + col)       = v0;
            *(__half2*)(g_proj + (size_t)(row + 8) * H_DIM + col) = v1;
        }
    }
}

// ---------------------------------------------------------------------------
// Recurrence: h = |proj_t + HH*h|, fp16 proj reads, 2 chains/thread,
// unroll 16 -> 64 B in flight per thread.
// ---------------------------------------------------------------------------
__global__ __launch_bounds__(256)
void recur_kernel(const float* __restrict__ HH) {
    const int i   = blockIdx.x * 256 + threadIdx.x;   // 0..BH/2-1
    const int idx = i * 2;                            // b*H + h, 2-aligned
    const float2 hh = *(const float2*)(HH + (idx & (H_DIM - 1)));
    const __half* p = g_proj + idx;
    float2 h = make_float2(0.f, 0.f);
#pragma unroll 16
    for (int t = 0; t < T_DIM; t++) {
        float2 a = __half22float2(*(const __half2*)(p + (size_t)t * BH));
        h.x = fabsf(fmaf(hh.x, h.x, a.x));
        h.y = fabsf(fmaf(hh.y, h.y, a.y));
    }
    *(float2*)(g_hfinal + idx) = h;
}

// ---------------------------------------------------------------------------
// GEMM2 split-K: partials over K chunks of 512, then reduce + bias.
// ---------------------------------------------------------------------------
__global__ __launch_bounds__(256)
void gemm2_part(const float* __restrict__ W) {
    __shared__ float As[16][36];
    __shared__ float Bs[16][68];

    const int tid = threadIdx.x;
    const int bm  = blockIdx.y * 32;
    const int bn  = blockIdx.x * 64;
    const int kz  = blockIdx.z;

    float acc[2][4] = {};
    const int tm = (tid >> 4) * 2;
    const int tn = (tid & 15) * 4;

    for (int k0 = kz * 512; k0 < kz * 512 + 512; k0 += 16) {
        if (tid < 128) {
            int row = tid >> 2, kq = (tid & 3) << 2;
            float4 av = *(const float4*)(g_hfinal + (size_t)(bm + row) * H_DIM + k0 + kq);
            As[kq + 0][row] = av.x; As[kq + 1][row] = av.y;
            As[kq + 2][row] = av.z; As[kq + 3][row] = av.w;
        }
        {
            int row = tid >> 2, kq = (tid & 3) << 2;
            float4 bv = *(const float4*)(W + (size_t)(bn + row) * H_DIM + k0 + kq);
            Bs[kq + 0][row] = bv.x; Bs[kq + 1][row] = bv.y;
            Bs[kq + 2][row] = bv.z; Bs[kq + 3][row] = bv.w;
        }
        __syncthreads();
#pragma unroll
        for (int kk = 0; kk < 16; kk++) {
            float a0 = As[kk][tm], a1 = As[kk][tm + 1];
            float4 b = *(const float4*)&Bs[kk][tn];
            acc[0][0] = fmaf(a0, b.x, acc[0][0]);
            acc[0][1] = fmaf(a0, b.y, acc[0][1]);
            acc[0][2] = fmaf(a0, b.z, acc[0][2]);
            acc[0][3] = fmaf(a0, b.w, acc[0][3]);
            acc[1][0] = fmaf(a1, b.x, acc[1][0]);
            acc[1][1] = fmaf(a1, b.y, acc[1][1]);
            acc[1][2] = fmaf(a1, b.z, acc[1][2]);
            acc[1][3] = fmaf(a1, b.w, acc[1][3]);
        }
        __syncthreads();
    }

    float* dst = g_part + (size_t)kz * (B_DIM * O_DIM);
#pragma unroll
    for (int i = 0; i < 2; i++) {
        float4 v = make_float4(acc[i][0], acc[i][1], acc[i][2], acc[i][3]);
        *(float4*)(dst + (size_t)(bm + tm + i) * O_DIM + bn + tn) = v;
    }
}

__global__ __launch_bounds__(256)
void gemm2_reduce(const float* __restrict__ bias, float* __restrict__ Y) {
    int i = blockIdx.x * 256 + threadIdx.x;          // 0..B*O-1
    float s = g_part[i] + g_part[B_DIM * O_DIM + i] +
              g_part[2 * B_DIM * O_DIM + i] + g_part[3 * B_DIM * O_DIM + i] +
              bias[i & (O_DIM - 1)];
    Y[i] = s;
}

// ---------------------------------------------------------------------------
extern "C" void kernel_launch(void* const* d_in, const int* in_sizes, int n_in,
                              void* d_out, int out_size) {
    (void)in_sizes; (void)n_in; (void)out_size;
    const float* X    = (const float*)d_in[0];   // [T,B,I]
    const float* W_IH = (const float*)d_in[1];   // [H,I]
    const float* HH   = (const float*)d_in[2];   // [H]
    const float* W_HO = (const float*)d_in[3];   // [O,H]
    const float* b_HO = (const float*)d_in[4];   // [O]
    float* Y = (float*)d_out;                    // [B,O]

    cudaFuncSetAttribute(gemm1_mma, cudaFuncAttributeMaxDynamicSharedMemorySize,
                         SMEM_DYN);

    // fp16 operand materialization
    convA_kernel<<<(M_DIM * I_DIM / 4) / 256, 256>>>(X);
    convB_kernel<<<(H_DIM * I_DIM / 4) / 256, 256>>>(W_IH);

    // proj = X @ W_IH^T, fp16 (K = 512), fp16 output
    gemm1_mma<<<dim3(H_DIM / 128, M_DIM / 256), 512, SMEM_DYN>>>();

    // sequential |.| recurrence over t
    recur_kernel<<<(BH / 2) / 256, 256>>>(HH);

    // Y = hfinal @ W_HO^T + b  (4-way split-K + reduce)
    gemm2_part<<<dim3(O_DIM / 64, B_DIM / 32, 4), 256>>>(W_HO);
    gemm2_reduce<<<(B_DIM * O_DIM) / 256, 256>>>(b_HO, Y);
}

// round 11
// speedup vs baseline: 1.1273x; 1.1273x over previous
#include <cuda_runtime.h>
#include <cuda_fp16.h>
#include <cstdint>

// Problem dims
#define T_DIM 256
#define B_DIM 128
#define I_DIM 512
#define H_DIM 2048
#define O_DIM 512
#define M_DIM (T_DIM * B_DIM)      // 32768
#define BH    (B_DIM * H_DIM)      // 262144
#define NSPLIT 8                   // gemm2 split-K ways

// Scratch (device globals: no allocation allowed)
__device__ static __half g_A2[(size_t)M_DIM * I_DIM];    // 32 MB fp16 X
__device__ static __half g_B2[(size_t)H_DIM * I_DIM];    // 2 MB  fp16 W_IH
__device__ static __half g_proj[(size_t)M_DIM * H_DIM];  // 128 MB fp16 proj
__device__ static float g_hfinal[BH];                    // 1 MB
__device__ static float g_part[NSPLIT * B_DIM * O_DIM];  // 2 MB (gemm2 split-K)

// ---------------------------------------------------------------------------
__device__ __forceinline__ uint32_t smem_u32(const void* p) {
    uint32_t a;
    asm("{ .reg .u64 t; cvta.to.shared.u64 t, %1; cvt.u32.u64 %0, t; }"
        : "=r"(a) : "l"(p));
    return a;
}

__device__ __forceinline__ void cp16(uint32_t dst, const void* src) {
    asm volatile("cp.async.cg.shared.global [%0], [%1], 16;" :: "r"(dst), "l"(src));
}
#define CP_COMMIT() asm volatile("cp.async.commit_group;" ::: "memory")
#define CP_WAIT(n)  asm volatile("cp.async.wait_group %0;" :: "n"(n) : "memory")

#define LDSM_X4(r0, r1, r2, r3, addr) \
    asm volatile("ldmatrix.sync.aligned.m8n8.x4.shared.b16 {%0,%1,%2,%3}, [%4];" \
                 : "=r"(r0), "=r"(r1), "=r"(r2), "=r"(r3) : "r"(addr))

#define MMA_FP16(d, a, b0, b1) \
    asm volatile("mma.sync.aligned.m16n8k16.row.col.f32.f16.f16.f32 " \
                 "{%0,%1,%2,%3}, {%4,%5,%6,%7}, {%8,%9}, {%0,%1,%2,%3};" \
                 : "+f"((d)[0]), "+f"((d)[1]), "+f"((d)[2]), "+f"((d)[3]) \
                 : "r"((a)[0]), "r"((a)[1]), "r"((a)[2]), "r"((a)[3]), \
                   "r"(b0), "r"(b1))

// ---------------------------------------------------------------------------
// Merged convert kernel: fp32 -> fp16 for X (A) and W_IH (B) in one launch.
// Blocks [0, NB_A) handle A; the rest handle B.
// ---------------------------------------------------------------------------
#define NB_A ((M_DIM * I_DIM / 4) / 256)   // 16384 blocks for A
#define NB_B ((H_DIM * I_DIM / 4) / 256)   // 1024 blocks for B

__global__ __launch_bounds__(256)
void conv_kernel(const float* __restrict__ X, const float* __restrict__ W) {
    const bool isA = blockIdx.x < NB_A;
    const int  bi  = isA ? blockIdx.x : blockIdx.x - NB_A;
    const int  i   = bi * 256 + threadIdx.x;
    const float* src = isA ? X : W;
    unsigned short* dst = (unsigned short*)(isA ? g_A2 : g_B2);

    float4 v = ((const float4*)src)[i];
    unsigned short hu[4];
    float f[4] = {v.x, v.y, v.z, v.w};
#pragma unroll
    for (int k = 0; k < 4; k++)
        hu[k] = __half_as_ushort(__float2half(f[k]));
    *(ushort4*)(dst + (size_t)i * 4) = make_ushort4(hu[0], hu[1], hu[2], hu[3]);
}

// ---------------------------------------------------------------------------
// GEMM1: proj[M, H] = A · B^T over K = 512 (fp16 mma.sync m16n8k16).
// CTA 128x128, 8 warps (2m x 4n), warp tile 64x32, 2 CTAs/SM, NS=3 cp.async.
// Register fragment double-buffering; SINGLE barrier per chunk (bottom
// barrier redundant: stage overwritten at iter j == stage read at j-1,
// already ordered by the top barrier of iter j).
// ---------------------------------------------------------------------------
#define NS       3
#define NIT      8
#define TILE_B   16384             // 128 x 128B
#define STAGE_B  32768             // A + B
#define SMEM_DYN (NS * STAGE_B)    // 98304

__global__ __launch_bounds__(256, 2)
void gemm1_mma() {
    extern __shared__ char dsm[];
    const uint32_t smem = smem_u32(dsm);

    const int tid  = threadIdx.x;
    const int lane = tid & 31;
    const int wid  = tid >> 5;
    const int wm   = wid & 1;          // m offset 0/64
    const int wn   = wid >> 1;         // n offset 0/32/64/96
    const int bm   = blockIdx.y * 128;
    const int bn   = blockIdx.x * 128;

    // ldmatrix lane geometry
    const int ra = (lane & 7) + ((lane >> 3) & 1) * 8;   // A row-in-tile
    const int ca = lane >> 4;                            // A c16 parity
    const int rb = (lane & 7) + (lane >> 4) * 8;         // B row-in-pairtile
    const int cb = (lane >> 3) & 1;                      // B c16 parity
    const int xr = lane & 7;                             // swizzle key

    float acc[4][4][4];
#pragma unroll
    for (int i = 0; i < 4; i++)
#pragma unroll
        for (int j = 0; j < 4; j++)
#pragma unroll
            for (int k = 0; k < 4; k++) acc[i][j][k] = 0.f;

    auto load_chunk = [&](int lt, int ls) {
        const char* Ab = (const char*)(g_A2 + (size_t)bm * I_DIM + lt * 64);
        const char* Bb = (const char*)(g_B2 + (size_t)bn * I_DIM + lt * 64);
        uint32_t sA = smem + ls * STAGE_B;
        uint32_t sB = sA + TILE_B;
#pragma unroll
        for (int i = 0; i < 4; i++) {
            int idx = tid + i * 256;              // 0..1023
            int r = idx >> 3, c = idx & 7;
            uint32_t sw = r * 128 + ((c ^ (r & 7)) * 16);
            cp16(sA + sw, Ab + (size_t)r * 1024 + c * 16);
        }
#pragma unroll
        for (int i = 0; i < 4; i++) {
            int idx = tid + i * 256;
            int r = idx >> 3, c = idx & 7;
            uint32_t sw = r * 128 + ((c ^ (r & 7)) * 16);
            cp16(sB + sw, Bb + (size_t)r * 1024 + c * 16);
        }
    };

    load_chunk(0, 0); CP_COMMIT();
    load_chunk(1, 1); CP_COMMIT();

    const uint32_t aRow = (uint32_t)(wm * 64 + ra) * 128;
    const uint32_t bRow = (uint32_t)(wn * 32 + rb) * 128;

    uint32_t a[2][4][4], b[2][2][4];   // double-buffered fragments

    auto load_frags = [&](uint32_t aB, uint32_t bB, int ks, int buf) {
#pragma unroll
        for (int mt = 0; mt < 4; mt++) {
            uint32_t addr = aB + aRow + mt * 16 * 128 +
                            (((ks * 2 + ca) ^ xr) * 16);
            LDSM_X4(a[buf][mt][0], a[buf][mt][1], a[buf][mt][2], a[buf][mt][3], addr);
        }
#pragma unroll
        for (int np = 0; np < 2; np++) {
            uint32_t addr = bB + bRow + np * 16 * 128 +
                            (((ks * 2 + cb) ^ xr) * 16);
            LDSM_X4(b[buf][np][0], b[buf][np][1], b[buf][np][2], b[buf][np][3], addr);
        }
    };

    for (int j = 0; j < NIT; j++) {
        CP_WAIT(1);
        __syncthreads();               // single barrier per chunk

        int nxt = j + 2;
        if (nxt < NIT) load_chunk(nxt, nxt % NS);
        CP_COMMIT();

        const uint32_t aB = smem + (j % NS) * STAGE_B;
        const uint32_t bB = aB + TILE_B;

        load_frags(aB, bB, 0, 0);
#pragma unroll
        for (int ks = 0; ks < 4; ks++) {
            const int cur = ks & 1;
            if (ks < 3) load_frags(aB, bB, ks + 1, cur ^ 1);
#pragma unroll
            for (int mt = 0; mt < 4; mt++)
#pragma unroll
                for (int nt = 0; nt < 4; nt++)
                    MMA_FP16(acc[mt][nt], a[cur][mt],
                             b[cur][nt >> 1][(nt & 1) * 2],
                             b[cur][nt >> 1][(nt & 1) * 2 + 1]);
        }
    }

    // epilogue: convert to fp16, half2 stores
    const int gq = lane >> 2;
    const int tq = lane & 3;
#pragma unroll
    for (int mt = 0; mt < 4; mt++) {
#pragma unroll
        for (int nt = 0; nt < 4; nt++) {
            int row = bm + wm * 64 + mt * 16 + gq;
            int col = bn + wn * 32 + nt * 8 + tq * 2;
            __half2 v0 = __floats2half2_rn(acc[mt][nt][0], acc[mt][nt][1]);
            __half2 v1 = __floats2half2_rn(acc[mt][nt][2], acc[mt][nt][3]);
            *(__half2*)(g_proj + (size_t)row * H_DIM + col)       = v0;
            *(__half2*)(g_proj + (size_t)(row + 8) * H_DIM + col) = v1;
        }
    }
}

// ---------------------------------------------------------------------------
// Recurrence: h = |proj_t + HH*h|, fp16 proj reads, 2 chains/thread,
// unroll 32 -> 128 B in flight per thread.
// ---------------------------------------------------------------------------
__global__ __launch_bounds__(256)
void recur_kernel(const float* __restrict__ HH) {
    const int i   = blockIdx.x * 256 + threadIdx.x;   // 0..BH/2-1
    const int idx = i * 2;                            // b*H + h, 2-aligned
    const float2 hh = *(const float2*)(HH + (idx & (H_DIM - 1)));
    const __half* p = g_proj + idx;
    float2 h = make_float2(0.f, 0.f);
#pragma unroll 32
    for (int t = 0; t < T_DIM; t++) {
        float2 a = __half22float2(*(const __half2*)(p + (size_t)t * BH));
        h.x = fabsf(fmaf(hh.x, h.x, a.x));
        h.y = fabsf(fmaf(hh.y, h.y, a.y));
    }
    *(float2*)(g_hfinal + idx) = h;
}

// ---------------------------------------------------------------------------
// GEMM2 split-K (8-way): partials over K chunks of 256, then reduce + bias.
// ---------------------------------------------------------------------------
__global__ __launch_bounds__(256)
void gemm2_part(const float* __restrict__ W) {
    __shared__ float As[16][36];
    __shared__ float Bs[16][68];

    const int tid = threadIdx.x;
    const int bm  = blockIdx.y * 32;
    const int bn  = blockIdx.x * 64;
    const int kz  = blockIdx.z;

    float acc[2][4] = {};
    const int tm = (tid >> 4) * 2;
    const int tn = (tid & 15) * 4;

    const int kbase = kz * (H_DIM / NSPLIT);         // 256 per split
    for (int k0 = kbase; k0 < kbase + H_DIM / NSPLIT; k0 += 16) {
        if (tid < 128) {
            int row = tid >> 2, kq = (tid & 3) << 2;
            float4 av = *(const float4*)(g_hfinal + (size_t)(bm + row) * H_DIM + k0 + kq);
            As[kq + 0][row] = av.x; As[kq + 1][row] = av.y;
            As[kq + 2][row] = av.z; As[kq + 3][row] = av.w;
        }
        {
            int row = tid >> 2, kq = (tid & 3) << 2;
            float4 bv = *(const float4*)(W + (size_t)(bn + row) * H_DIM + k0 + kq);
            Bs[kq + 0][row] = bv.x; Bs[kq + 1][row] = bv.y;
            Bs[kq + 2][row] = bv.z; Bs[kq + 3][row] = bv.w;
        }
        __syncthreads();
#pragma unroll
        for (int kk = 0; kk < 16; kk++) {
            float a0 = As[kk][tm], a1 = As[kk][tm + 1];
            float4 b = *(const float4*)&Bs[kk][tn];
            acc[0][0] = fmaf(a0, b.x, acc[0][0]);
            acc[0][1] = fmaf(a0, b.y, acc[0][1]);
            acc[0][2] = fmaf(a0, b.z, acc[0][2]);
            acc[0][3] = fmaf(a0, b.w, acc[0][3]);
            acc[1][0] = fmaf(a1, b.x, acc[1][0]);
            acc[1][1] = fmaf(a1, b.y, acc[1][1]);
            acc[1][2] = fmaf(a1, b.z, acc[1][2]);
            acc[1][3] = fmaf(a1, b.w, acc[1][3]);
        }
        __syncthreads();
    }

    float* dst = g_part + (size_t)kz * (B_DIM * O_DIM);
#pragma unroll
    for (int i = 0; i < 2; i++) {
        float4 v = make_float4(acc[i][0], acc[i][1], acc[i][2], acc[i][3]);
        *(float4*)(dst + (size_t)(bm + tm + i) * O_DIM + bn + tn) = v;
    }
}

__global__ __launch_bounds__(256)
void gemm2_reduce(const float* __restrict__ bias, float* __restrict__ Y) {
    int i = blockIdx.x * 256 + threadIdx.x;          // 0..B*O-1
    float s = bias[i & (O_DIM - 1)];
#pragma unroll
    for (int z = 0; z < NSPLIT; z++)
        s += g_part[(size_t)z * (B_DIM * O_DIM) + i];
    Y[i] = s;
}

// ---------------------------------------------------------------------------
extern "C" void kernel_launch(void* const* d_in, const int* in_sizes, int n_in,
                              void* d_out, int out_size) {
    (void)in_sizes; (void)n_in; (void)out_size;
    const float* X    = (const float*)d_in[0];   // [T,B,I]
    const float* W_IH = (const float*)d_in[1];   // [H,I]
    const float* HH   = (const float*)d_in[2];   // [H]
    const float* W_HO = (const float*)d_in[3];   // [O,H]
    const float* b_HO = (const float*)d_in[4];   // [O]
    float* Y = (float*)d_out;                    // [B,O]

    cudaFuncSetAttribute(gemm1_mma, cudaFuncAttributeMaxDynamicSharedMemorySize,
                         SMEM_DYN);

    // fp16 operand materialization (A and B in one launch)
    conv_kernel<<<NB_A + NB_B, 256>>>(X, W_IH);

    // proj = X @ W_IH^T, fp16 (K = 512), fp16 output
    gemm1_mma<<<dim3(H_DIM / 128, M_DIM / 128), 256, SMEM_DYN>>>();

    // sequential |.| recurrence over t
    recur_kernel<<<(BH / 2) / 256, 256>>>(HH);

    // Y = hfinal @ W_HO^T + b  (8-way split-K + reduce)
    gemm2_part<<<dim3(O_DIM / 64, B_DIM / 32, NSPLIT), 256>>>(W_HO);
    gemm2_reduce<<<(B_DIM * O_DIM) / 256, 256>>>(b_HO, Y);
}

// round 13
// speedup vs baseline: 1.1930x; 1.0583x over previous
#include <cuda_runtime.h>
#include <cuda_fp16.h>
#include <cstdint>

// Problem dims
#define T_DIM 256
#define B_DIM 128
#define I_DIM 512
#define H_DIM 2048
#define O_DIM 512
#define M_DIM (T_DIM * B_DIM)      // 32768
#define BH    (B_DIM * H_DIM)      // 262144
#define NSPLIT2 16                 // gemm2 split-K ways

// Scratch (device globals: no allocation allowed)
__device__ static __half g_A2[(size_t)M_DIM * I_DIM];    // 32 MB fp16 X
__device__ static __half g_B2[(size_t)H_DIM * I_DIM];    // 2 MB  fp16 W_IH
__device__ static __half g_W2[(size_t)O_DIM * H_DIM];    // 2 MB  fp16 W_HO
__device__ static __half g_proj[(size_t)M_DIM * H_DIM];  // 128 MB fp16 proj
__device__ static __half g_hfinal[BH];                   // 0.5 MB fp16
__device__ static float g_part[NSPLIT2 * B_DIM * O_DIM]; // 4 MB (gemm2 split-K)

// ---------------------------------------------------------------------------
__device__ __forceinline__ uint32_t smem_u32(const void* p) {
    uint32_t a;
    asm("{ .reg .u64 t; cvta.to.shared.u64 t, %1; cvt.u32.u64 %0, t; }"
        : "=r"(a) : "l"(p));
    return a;
}

__device__ __forceinline__ void cp16(uint32_t dst, const void* src) {
    asm volatile("cp.async.cg.shared.global [%0], [%1], 16;" :: "r"(dst), "l"(src));
}
#define CP_COMMIT() asm volatile("cp.async.commit_group;" ::: "memory")
#define CP_WAIT(n)  asm volatile("cp.async.wait_group %0;" :: "n"(n) : "memory")

#define LDSM_X4(r0, r1, r2, r3, addr) \
    asm volatile("ldmatrix.sync.aligned.m8n8.x4.shared.b16 {%0,%1,%2,%3}, [%4];" \
                 : "=r"(r0), "=r"(r1), "=r"(r2), "=r"(r3) : "r"(addr))

#define MMA_FP16(d, a, b0, b1) \
    asm volatile("mma.sync.aligned.m16n8k16.row.col.f32.f16.f16.f32 " \
                 "{%0,%1,%2,%3}, {%4,%5,%6,%7}, {%8,%9}, {%0,%1,%2,%3};" \
                 : "+f"((d)[0]), "+f"((d)[1]), "+f"((d)[2]), "+f"((d)[3]) \
                 : "r"((a)[0]), "r"((a)[1]), "r"((a)[2]), "r"((a)[3]), \
                   "r"(b0), "r"(b1))

// ---------------------------------------------------------------------------
// Merged convert kernel: fp32 -> fp16 for X, W_IH, W_HO in one launch.
// ---------------------------------------------------------------------------
#define NB_A ((M_DIM * I_DIM / 4) / 256)   // 16384 blocks
#define NB_B ((H_DIM * I_DIM / 4) / 256)   // 1024 blocks
#define NB_W ((O_DIM * H_DIM / 4) / 256)   // 1024 blocks

__global__ __launch_bounds__(256)
void conv_kernel(const float* __restrict__ X, const float* __restrict__ WIH,
                 const float* __restrict__ WHO) {
    const float* src;
    unsigned short* dst;
    int bi;
    if (blockIdx.x < NB_A)            { src = X;   dst = (unsigned short*)g_A2; bi = blockIdx.x; }
    else if (blockIdx.x < NB_A + NB_B){ src = WIH; dst = (unsigned short*)g_B2; bi = blockIdx.x - NB_A; }
    else                              { src = WHO; dst = (unsigned short*)g_W2; bi = blockIdx.x - NB_A - NB_B; }
    const int i = bi * 256 + threadIdx.x;

    float4 v = ((const float4*)src)[i];
    unsigned short hu[4];
    float f[4] = {v.x, v.y, v.z, v.w};
#pragma unroll
    for (int k = 0; k < 4; k++)
        hu[k] = __half_as_ushort(__float2half(f[k]));
    *(ushort4*)(dst + (size_t)i * 4) = make_ushort4(hu[0], hu[1], hu[2], hu[3]);
}

// ---------------------------------------------------------------------------
// GEMM1: proj[M, H] = A · B^T over K = 512 (fp16 mma.sync m16n8k16).
// CTA 128x128, 8 warps (2m x 4n), warp tile 64x32, 2 CTAs/SM, NS=3 cp.async.
// Register fragment double-buffering; single barrier per chunk.
// ---------------------------------------------------------------------------
#define NS       3
#define NIT      8
#define TILE_B   16384             // 128 x 128B
#define STAGE_B  32768             // A + B
#define SMEM_DYN (NS * STAGE_B)    // 98304

__global__ __launch_bounds__(256, 2)
void gemm1_mma() {
    extern __shared__ char dsm[];
    const uint32_t smem = smem_u32(dsm);

    const int tid  = threadIdx.x;
    const int lane = tid & 31;
    const int wid  = tid >> 5;
    const int wm   = wid & 1;          // m offset 0/64
    const int wn   = wid >> 1;         // n offset 0/32/64/96
    const int bm   = blockIdx.y * 128;
    const int bn   = blockIdx.x * 128;

    const int ra = (lane & 7) + ((lane >> 3) & 1) * 8;
    const int ca = lane >> 4;
    const int rb = (lane & 7) + (lane >> 4) * 8;
    const int cb = (lane >> 3) & 1;
    const int xr = lane & 7;

    float acc[4][4][4];
#pragma unroll
    for (int i = 0; i < 4; i++)
#pragma unroll
        for (int j = 0; j < 4; j++)
#pragma unroll
            for (int k = 0; k < 4; k++) acc[i][j][k] = 0.f;

    auto load_chunk = [&](int lt, int ls) {
        const char* Ab = (const char*)(g_A2 + (size_t)bm * I_DIM + lt * 64);
        const char* Bb = (const char*)(g_B2 + (size_t)bn * I_DIM + lt * 64);
        uint32_t sA = smem + ls * STAGE_B;
        uint32_t sB = sA + TILE_B;
#pragma unroll
        for (int i = 0; i < 4; i++) {
            int idx = tid + i * 256;
            int r = idx >> 3, c = idx & 7;
            uint32_t sw = r * 128 + ((c ^ (r & 7)) * 16);
            cp16(sA + sw, Ab + (size_t)r * 1024 + c * 16);
        }
#pragma unroll
        for (int i = 0; i < 4; i++) {
            int idx = tid + i * 256;
            int r = idx >> 3, c = idx & 7;
            uint32_t sw = r * 128 + ((c ^ (r & 7)) * 16);
            cp16(sB + sw, Bb + (size_t)r * 1024 + c * 16);
        }
    };

    load_chunk(0, 0); CP_COMMIT();
    load_chunk(1, 1); CP_COMMIT();

    const uint32_t aRow = (uint32_t)(wm * 64 + ra) * 128;
    const uint32_t bRow = (uint32_t)(wn * 32 + rb) * 128;

    uint32_t a[2][4][4], b[2][2][4];

    auto load_frags = [&](uint32_t aB, uint32_t bB, int ks, int buf) {
#pragma unroll
        for (int mt = 0; mt < 4; mt++) {
            uint32_t addr = aB + aRow + mt * 16 * 128 +
                            (((ks * 2 + ca) ^ xr) * 16);
            LDSM_X4(a[buf][mt][0], a[buf][mt][1], a[buf][mt][2], a[buf][mt][3], addr);
        }
#pragma unroll
        for (int np = 0; np < 2; np++) {
            uint32_t addr = bB + bRow + np * 16 * 128 +
                            (((ks * 2 + cb) ^ xr) * 16);
            LDSM_X4(b[buf][np][0], b[buf][np][1], b[buf][np][2], b[buf][np][3], addr);
        }
    };

    for (int j = 0; j < NIT; j++) {
        CP_WAIT(1);
        __syncthreads();

        int nxt = j + 2;
        if (nxt < NIT) load_chunk(nxt, nxt % NS);
        CP_COMMIT();

        const uint32_t aB = smem + (j % NS) * STAGE_B;
        const uint32_t bB = aB + TILE_B;

        load_frags(aB, bB, 0, 0);
#pragma unroll
        for (int ks = 0; ks < 4; ks++) {
            const int cur = ks & 1;
            if (ks < 3) load_frags(aB, bB, ks + 1, cur ^ 1);
#pragma unroll
            for (int mt = 0; mt < 4; mt++)
#pragma unroll
                for (int nt = 0; nt < 4; nt++)
                    MMA_FP16(acc[mt][nt], a[cur][mt],
                             b[cur][nt >> 1][(nt & 1) * 2],
                             b[cur][nt >> 1][(nt & 1) * 2 + 1]);
        }
    }

    const int gq = lane >> 2;
    const int tq = lane & 3;
#pragma unroll
    for (int mt = 0; mt < 4; mt++) {
#pragma unroll
        for (int nt = 0; nt < 4; nt++) {
            int row = bm + wm * 64 + mt * 16 + gq;
            int col = bn + wn * 32 + nt * 8 + tq * 2;
            __half2 v0 = __floats2half2_rn(acc[mt][nt][0], acc[mt][nt][1]);
            __half2 v1 = __floats2half2_rn(acc[mt][nt][2], acc[mt][nt][3]);
            *(__half2*)(g_proj + (size_t)row * H_DIM + col)       = v0;
            *(__half2*)(g_proj + (size_t)(row + 8) * H_DIM + col) = v1;
        }
    }
}

// ---------------------------------------------------------------------------
// Recurrence: h = |proj_t + HH*h|, fp16 reads, 2 chains/thread, unroll 32.
// Writes h_final as fp16 (feeds tensor-core gemm2).
// ---------------------------------------------------------------------------
__global__ __launch_bounds__(256)
void recur_kernel(const float* __restrict__ HH) {
    const int i   = blockIdx.x * 256 + threadIdx.x;   // 0..BH/2-1
    const int idx = i * 2;                            // b*H + h, 2-aligned
    const float2 hh = *(const float2*)(HH + (idx & (H_DIM - 1)));
    const __half* p = g_proj + idx;
    float2 h = make_float2(0.f, 0.f);
#pragma unroll 32
    for (int t = 0; t < T_DIM; t++) {
        float2 a = __half22float2(*(const __half2*)(p + (size_t)t * BH));
        h.x = fabsf(fmaf(hh.x, h.x, a.x));
        h.y = fabsf(fmaf(hh.y, h.y, a.y));
    }
    *(__half2*)(g_hfinal + idx) = __floats2half2_rn(h.x, h.y);
}

// ---------------------------------------------------------------------------
// GEMM2 (tensor core): part[kz] = hfinal[128, K-chunk] · W2[O-tile, K-chunk]^T
// Grid (4 N-tiles, 16 K-splits); each CTA 128x128 x K=128 (2 chunks of 64).
// Same smem swizzle/LDSM/MMA as gemm1; no pipeline (2 chunks preloaded).
// ---------------------------------------------------------------------------
#define G2_SMEM (2 * STAGE_B)      // 65536

__global__ __launch_bounds__(256, 1)
void gemm2_mma() {
    extern __shared__ char dsm[];
    const uint32_t smem = smem_u32(dsm);

    const int tid  = threadIdx.x;
    const int lane = tid & 31;
    const int wid  = tid >> 5;
    const int wm   = wid & 1;
    const int wn   = wid >> 1;
    const int bn   = blockIdx.x * 128;      // O tile
    const int kz   = blockIdx.y;            // K split
    const int k0   = kz * (H_DIM / NSPLIT2);   // 128-wide K window

    const int ra = (lane & 7) + ((lane >> 3) & 1) * 8;
    const int ca = lane >> 4;
    const int rb = (lane & 7) + (lane >> 4) * 8;
    const int cb = (lane >> 3) & 1;
    const int xr = lane & 7;

    float acc[4][4][4];
#pragma unroll
    for (int i = 0; i < 4; i++)
#pragma unroll
        for (int j = 0; j < 4; j++)
#pragma unroll
            for (int k = 0; k < 4; k++) acc[i][j][k] = 0.f;

    // preload both 64-wide chunks (A rows: hfinal 128 x H; B rows: W2 O x H)
#pragma unroll
    for (int lt = 0; lt < 2; lt++) {
        const char* Ab = (const char*)(g_hfinal) + (size_t)(k0 + lt * 64) * 2;
        const char* Bb = (const char*)(g_W2 + (size_t)bn * H_DIM + k0 + lt * 64);
        uint32_t sA = smem + lt * STAGE_B;
        uint32_t sB = sA + TILE_B;
#pragma unroll
        for (int i = 0; i < 4; i++) {
            int idx = tid + i * 256;
            int r = idx >> 3, c = idx & 7;
            uint32_t sw = r * 128 + ((c ^ (r & 7)) * 16);
            cp16(sA + sw, Ab + (size_t)r * (H_DIM * 2) + c * 16);
        }
#pragma unroll
        for (int i = 0; i < 4; i++) {
            int idx = tid + i * 256;
            int r = idx >> 3, c = idx & 7;
            uint32_t sw = r * 128 + ((c ^ (r & 7)) * 16);
            cp16(sB + sw, Bb + (size_t)r * (H_DIM * 2) + c * 16);
        }
    }
    CP_COMMIT();
    CP_WAIT(0);
    __syncthreads();

    const uint32_t aRow = (uint32_t)(wm * 64 + ra) * 128;
    const uint32_t bRow = (uint32_t)(wn * 32 + rb) * 128;

#pragma unroll
    for (int j = 0; j < 2; j++) {
        const uint32_t aB = smem + j * STAGE_B;
        const uint32_t bB = aB + TILE_B;
#pragma unroll
        for (int ks = 0; ks < 4; ks++) {
            uint32_t a[4][4], b[2][4];
#pragma unroll
            for (int mt = 0; mt < 4; mt++) {
                uint32_t addr = aB + aRow + mt * 16 * 128 +
                                (((ks * 2 + ca) ^ xr) * 16);
                LDSM_X4(a[mt][0], a[mt][1], a[mt][2], a[mt][3], addr);
            }
#pragma unroll
            for (int np = 0; np < 2; np++) {
                uint32_t addr = bB + bRow + np * 16 * 128 +
                                (((ks * 2 + cb) ^ xr) * 16);
                LDSM_X4(b[np][0], b[np][1], b[np][2], b[np][3], addr);
            }
#pragma unroll
            for (int mt = 0; mt < 4; mt++)
#pragma unroll
                for (int nt = 0; nt < 4; nt++)
                    MMA_FP16(acc[mt][nt], a[mt],
                             b[nt >> 1][(nt & 1) * 2], b[nt >> 1][(nt & 1) * 2 + 1]);
        }
    }

    float* dst = g_part + (size_t)kz * (B_DIM * O_DIM);
    const int gq = lane >> 2;
    const int tq = lane & 3;
#pragma unroll
    for (int mt = 0; mt < 4; mt++) {
#pragma unroll
        for (int nt = 0; nt < 4; nt++) {
            int row = wm * 64 + mt * 16 + gq;
            int col = bn + wn * 32 + nt * 8 + tq * 2;
            *(float2*)(dst + (size_t)row * O_DIM + col) =
                make_float2(acc[mt][nt][0], acc[mt][nt][1]);
            *(float2*)(dst + (size_t)(row + 8) * O_DIM + col) =
                make_float2(acc[mt][nt][2], acc[mt][nt][3]);
        }
    }
}

__global__ __launch_bounds__(256)
void gemm2_reduce(const float* __restrict__ bias, float* __restrict__ Y) {
    int i = blockIdx.x * 256 + threadIdx.x;          // 0..B*O-1
    float s = bias[i & (O_DIM - 1)];
#pragma unroll
    for (int z = 0; z < NSPLIT2; z++)
        s += g_part[(size_t)z * (B_DIM * O_DIM) + i];
    Y[i] = s;
}

// ---------------------------------------------------------------------------
extern "C" void kernel_launch(void* const* d_in, const int* in_sizes, int n_in,
                              void* d_out, int out_size) {
    (void)in_sizes; (void)n_in; (void)out_size;
    const float* X    = (const float*)d_in[0];   // [T,B,I]
    const float* W_IH = (const float*)d_in[1];   // [H,I]
    const float* HH   = (const float*)d_in[2];   // [H]
    const float* W_HO = (const float*)d_in[3];   // [O,H]
    const float* b_HO = (const float*)d_in[4];   // [O]
    float* Y = (float*)d_out;                    // [B,O]

    cudaFuncSetAttribute(gemm1_mma, cudaFuncAttributeMaxDynamicSharedMemorySize,
                         SMEM_DYN);
    cudaFuncSetAttribute(gemm2_mma, cudaFuncAttributeMaxDynamicSharedMemorySize,
                         G2_SMEM);

    // fp16 operand materialization (X, W_IH, W_HO in one launch)
    conv_kernel<<<NB_A + NB_B + NB_W, 256>>>(X, W_IH, W_HO);

    // proj = X @ W_IH^T, fp16 (K = 512), fp16 output
    gemm1_mma<<<dim3(H_DIM / 128, M_DIM / 128), 256, SMEM_DYN>>>();

    // sequential |.| recurrence over t -> fp16 hfinal
    recur_kernel<<<(BH / 2) / 256, 256>>>(HH);

    // Y = hfinal @ W_HO^T + b  (tensor-core, 16-way split-K + reduce)
    gemm2_mma<<<dim3(O_DIM / 128, NSPLIT2), 256, G2_SMEM>>>();
    gemm2_reduce<<<(B_DIM * O_DIM) / 256, 256>>>(b_HO, Y);
}

// round 15
// speedup vs baseline: 1.2439x; 1.0427x over previous
#include <cuda_runtime.h>
#include <cuda_fp16.h>
#include <cstdint>

// Problem dims
#define T_DIM 256
#define B_DIM 128
#define I_DIM 512
#define H_DIM 2048
#define O_DIM 512
#define M_DIM (T_DIM * B_DIM)      // 32768
#define BH    (B_DIM * H_DIM)      // 262144
#define NSPLIT2 32                 // gemm2 split-K ways (64-wide K windows)

// Scratch (device globals: no allocation allowed)
__device__ static __half g_A2[(size_t)M_DIM * I_DIM];    // 32 MB fp16 X
__device__ static __half g_B2[(size_t)H_DIM * I_DIM];    // 2 MB  fp16 W_IH
__device__ static __half g_W2[(size_t)O_DIM * H_DIM];    // 2 MB  fp16 W_HO
__device__ static __half g_proj[(size_t)M_DIM * H_DIM];  // 128 MB fp16 proj
__device__ static __half g_hfinal[BH];                   // 0.5 MB fp16
__device__ static float g_part[NSPLIT2 * B_DIM * O_DIM]; // 8 MB (gemm2 split-K)

// ---------------------------------------------------------------------------
__device__ __forceinline__ uint32_t smem_u32(const void* p) {
    uint32_t a;
    asm("{ .reg .u64 t; cvta.to.shared.u64 t, %1; cvt.u32.u64 %0, t; }"
        : "=r"(a) : "l"(p));
    return a;
}

__device__ __forceinline__ void cp16(uint32_t dst, const void* src) {
    asm volatile("cp.async.cg.shared.global [%0], [%1], 16;" :: "r"(dst), "l"(src));
}
#define CP_COMMIT() asm volatile("cp.async.commit_group;" ::: "memory")
#define CP_WAIT(n)  asm volatile("cp.async.wait_group %0;" :: "n"(n) : "memory")

#define LDSM_X4(r0, r1, r2, r3, addr) \
    asm volatile("ldmatrix.sync.aligned.m8n8.x4.shared.b16 {%0,%1,%2,%3}, [%4];" \
                 : "=r"(r0), "=r"(r1), "=r"(r2), "=r"(r3) : "r"(addr))

#define MMA_FP16(d, a, b0, b1) \
    asm volatile("mma.sync.aligned.m16n8k16.row.col.f32.f16.f16.f32 " \
                 "{%0,%1,%2,%3}, {%4,%5,%6,%7}, {%8,%9}, {%0,%1,%2,%3};" \
                 : "+f"((d)[0]), "+f"((d)[1]), "+f"((d)[2]), "+f"((d)[3]) \
                 : "r"((a)[0]), "r"((a)[1]), "r"((a)[2]), "r"((a)[3]), \
                   "r"(b0), "r"(b1))

// ---------------------------------------------------------------------------
// Merged convert kernel: fp32 -> fp16 for X, W_IH, W_HO; 8 elems/thread.
// ---------------------------------------------------------------------------
#define NB_A ((M_DIM * I_DIM / 8) / 256)   // 8192 blocks
#define NB_B ((H_DIM * I_DIM / 8) / 256)   // 512 blocks
#define NB_W ((O_DIM * H_DIM / 8) / 256)   // 512 blocks

__global__ __launch_bounds__(256)
void conv_kernel(const float* __restrict__ X, const float* __restrict__ WIH,
                 const float* __restrict__ WHO) {
    const float* src;
    unsigned short* dst;
    int bi;
    if (blockIdx.x < NB_A)            { src = X;   dst = (unsigned short*)g_A2; bi = blockIdx.x; }
    else if (blockIdx.x < NB_A + NB_B){ src = WIH; dst = (unsigned short*)g_B2; bi = blockIdx.x - NB_A; }
    else                              { src = WHO; dst = (unsigned short*)g_W2; bi = blockIdx.x - NB_A - NB_B; }
    const int i = bi * 256 + threadIdx.x;   // handles float4 pair (i*2, i*2+1)

    float4 v0 = ((const float4*)src)[i * 2];
    float4 v1 = ((const float4*)src)[i * 2 + 1];
    float f[8] = {v0.x, v0.y, v0.z, v0.w, v1.x, v1.y, v1.z, v1.w};
    unsigned short hu[8];
#pragma unroll
    for (int k = 0; k < 8; k++)
        hu[k] = __half_as_ushort(__float2half(f[k]));
    *(ushort4*)(dst + (size_t)i * 8)     = make_ushort4(hu[0], hu[1], hu[2], hu[3]);
    *(ushort4*)(dst + (size_t)i * 8 + 4) = make_ushort4(hu[4], hu[5], hu[6], hu[7]);
}

// ---------------------------------------------------------------------------
// GEMM1: proj[M, H] = A · B^T over K = 512 (fp16 mma.sync m16n8k16).
// CTA 128x128, 8 warps (2m x 4n), warp tile 64x32, 2 CTAs/SM, NS=3 cp.async.
// Register fragment double-buffering; single barrier per chunk.
// (At the legacy-HMMA fp32-acc issue peak: 512 MAC/cyc/SM. Do not touch.)
// ---------------------------------------------------------------------------
#define NS       3
#define NIT      8
#define TILE_B   16384             // 128 x 128B
#define STAGE_B  32768             // A + B
#define SMEM_DYN (NS * STAGE_B)    // 98304

__global__ __launch_bounds__(256, 2)
void gemm1_mma() {
    extern __shared__ char dsm[];
    const uint32_t smem = smem_u32(dsm);

    const int tid  = threadIdx.x;
    const int lane = tid & 31;
    const int wid  = tid >> 5;
    const int wm   = wid & 1;          // m offset 0/64
    const int wn   = wid >> 1;         // n offset 0/32/64/96
    const int bm   = blockIdx.y * 128;
    const int bn   = blockIdx.x * 128;

    const int ra = (lane & 7) + ((lane >> 3) & 1) * 8;
    const int ca = lane >> 4;
    const int rb = (lane & 7) + (lane >> 4) * 8;
    const int cb = (lane >> 3) & 1;
    const int xr = lane & 7;

    float acc[4][4][4];
#pragma unroll
    for (int i = 0; i < 4; i++)
#pragma unroll
        for (int j = 0; j < 4; j++)
#pragma unroll
            for (int k = 0; k < 4; k++) acc[i][j][k] = 0.f;

    auto load_chunk = [&](int lt, int ls) {
        const char* Ab = (const char*)(g_A2 + (size_t)bm * I_DIM + lt * 64);
        const char* Bb = (const char*)(g_B2 + (size_t)bn * I_DIM + lt * 64);
        uint32_t sA = smem + ls * STAGE_B;
        uint32_t sB = sA + TILE_B;
#pragma unroll
        for (int i = 0; i < 4; i++) {
            int idx = tid + i * 256;
            int r = idx >> 3, c = idx & 7;
            uint32_t sw = r * 128 + ((c ^ (r & 7)) * 16);
            cp16(sA + sw, Ab + (size_t)r * 1024 + c * 16);
        }
#pragma unroll
        for (int i = 0; i < 4; i++) {
            int idx = tid + i * 256;
            int r = idx >> 3, c = idx & 7;
            uint32_t sw = r * 128 + ((c ^ (r & 7)) * 16);
            cp16(sB + sw, Bb + (size_t)r * 1024 + c * 16);
        }
    };

    load_chunk(0, 0); CP_COMMIT();
    load_chunk(1, 1); CP_COMMIT();

    const uint32_t aRow = (uint32_t)(wm * 64 + ra) * 128;
    const uint32_t bRow = (uint32_t)(wn * 32 + rb) * 128;

    uint32_t a[2][4][4], b[2][2][4];

    auto load_frags = [&](uint32_t aB, uint32_t bB, int ks, int buf) {
#pragma unroll
        for (int mt = 0; mt < 4; mt++) {
            uint32_t addr = aB + aRow + mt * 16 * 128 +
                            (((ks * 2 + ca) ^ xr) * 16);
            LDSM_X4(a[buf][mt][0], a[buf][mt][1], a[buf][mt][2], a[buf][mt][3], addr);
        }
#pragma unroll
        for (int np = 0; np < 2; np++) {
            uint32_t addr = bB + bRow + np * 16 * 128 +
                            (((ks * 2 + cb) ^ xr) * 16);
            LDSM_X4(b[buf][np][0], b[buf][np][1], b[buf][np][2], b[buf][np][3], addr);
        }
    };

    for (int j = 0; j < NIT; j++) {
        CP_WAIT(1);
        __syncthreads();

        int nxt = j + 2;
        if (nxt < NIT) load_chunk(nxt, nxt % NS);
        CP_COMMIT();

        const uint32_t aB = smem + (j % NS) * STAGE_B;
        const uint32_t bB = aB + TILE_B;

        load_frags(aB, bB, 0, 0);
#pragma unroll
        for (int ks = 0; ks < 4; ks++) {
            const int cur = ks & 1;
            if (ks < 3) load_frags(aB, bB, ks + 1, cur ^ 1);
#pragma unroll
            for (int mt = 0; mt < 4; mt++)
#pragma unroll
                for (int nt = 0; nt < 4; nt++)
                    MMA_FP16(acc[mt][nt], a[cur][mt],
                             b[cur][nt >> 1][(nt & 1) * 2],
                             b[cur][nt >> 1][(nt & 1) * 2 + 1]);
        }
    }

    const int gq = lane >> 2;
    const int tq = lane & 3;
#pragma unroll
    for (int mt = 0; mt < 4; mt++) {
#pragma unroll
        for (int nt = 0; nt < 4; nt++) {
            int row = bm + wm * 64 + mt * 16 + gq;
            int col = bn + wn * 32 + nt * 8 + tq * 2;
            __half2 v0 = __floats2half2_rn(acc[mt][nt][0], acc[mt][nt][1]);
            __half2 v1 = __floats2half2_rn(acc[mt][nt][2], acc[mt][nt][3]);
            *(__half2*)(g_proj + (size_t)row * H_DIM + col)       = v0;
            *(__half2*)(g_proj + (size_t)(row + 8) * H_DIM + col) = v1;
        }
    }
}

// ---------------------------------------------------------------------------
// Recurrence: h = |proj_t + HH*h|, streaming (__ldcs) fp16 reads,
// 2 chains/thread, unroll 32. Writes fp16 hfinal.
// ---------------------------------------------------------------------------
__global__ __launch_bounds__(256)
void recur_kernel(const float* __restrict__ HH) {
    const int i   = blockIdx.x * 256 + threadIdx.x;   // 0..BH/2-1
    const int idx = i * 2;                            // b*H + h, 2-aligned
    const float2 hh = *(const float2*)(HH + (idx & (H_DIM - 1)));
    const __half2* p = (const __half2*)(g_proj + idx);
    float2 h = make_float2(0.f, 0.f);
#pragma unroll 32
    for (int t = 0; t < T_DIM; t++) {
        float2 a = __half22float2(__ldcs(p + (size_t)t * (BH / 2)));
        h.x = fabsf(fmaf(hh.x, h.x, a.x));
        h.y = fabsf(fmaf(hh.y, h.y, a.y));
    }
    *(__half2*)(g_hfinal + idx) = __floats2half2_rn(h.x, h.y);
}

// ---------------------------------------------------------------------------
// GEMM2 (tensor core): part[kz] = hfinal[128, K64] · W2[O-tile, K64]^T
// Grid (4 N-tiles, 32 K-splits) = 128 CTAs; one 64-wide chunk each.
// ---------------------------------------------------------------------------
#define G2_SMEM STAGE_B            // 32768

__global__ __launch_bounds__(256, 1)
void gemm2_mma() {
    extern __shared__ char dsm[];
    const uint32_t smem = smem_u32(dsm);

    const int tid  = threadIdx.x;
    const int lane = tid & 31;
    const int wid  = tid >> 5;
    const int wm   = wid & 1;
    const int wn   = wid >> 1;
    const int bn   = blockIdx.x * 128;      // O tile
    const int kz   = blockIdx.y;            // K split
    const int k0   = kz * (H_DIM / NSPLIT2);   // 64-wide K window

    const int ra = (lane & 7) + ((lane >> 3) & 1) * 8;
    const int ca = lane >> 4;
    const int rb = (lane & 7) + (lane >> 4) * 8;
    const int cb = (lane >> 3) & 1;
    const int xr = lane & 7;

    float acc[4][4][4];
#pragma unroll
    for (int i = 0; i < 4; i++)
#pragma unroll
        for (int j = 0; j < 4; j++)
#pragma unroll
            for (int k = 0; k < 4; k++) acc[i][j][k] = 0.f;

    // preload the 64-wide chunk (A rows: hfinal 128 x H; B rows: W2 O x H)
    {
        const char* Ab = (const char*)(g_hfinal) + (size_t)k0 * 2;
        const char* Bb = (const char*)(g_W2 + (size_t)bn * H_DIM + k0);
        uint32_t sA = smem;
        uint32_t sB = sA + TILE_B;
#pragma unroll
        for (int i = 0; i < 4; i++) {
            int idx = tid + i * 256;
            int r = idx >> 3, c = idx & 7;
            uint32_t sw = r * 128 + ((c ^ (r & 7)) * 16);
            cp16(sA + sw, Ab + (size_t)r * (H_DIM * 2) + c * 16);
        }
#pragma unroll
        for (int i = 0; i < 4; i++) {
            int idx = tid + i * 256;
            int r = idx >> 3, c = idx & 7;
            uint32_t sw = r * 128 + ((c ^ (r & 7)) * 16);
            cp16(sB + sw, Bb + (size_t)r * (H_DIM * 2) + c * 16);
        }
    }
    CP_COMMIT();
    CP_WAIT(0);
    __syncthreads();

    const uint32_t aRow = (uint32_t)(wm * 64 + ra) * 128;
    const uint32_t bRow = (uint32_t)(wn * 32 + rb) * 128;

#pragma unroll
    for (int ks = 0; ks < 4; ks++) {
        uint32_t a[4][4], b[2][4];
#pragma unroll
        for (int mt = 0; mt < 4; mt++) {
            uint32_t addr = smem + aRow + mt * 16 * 128 +
                            (((ks * 2 + ca) ^ xr) * 16);
            LDSM_X4(a[mt][0], a[mt][1], a[mt][2], a[mt][3], addr);
        }
#pragma unroll
        for (int np = 0; np < 2; np++) {
            uint32_t addr = smem + TILE_B + bRow + np * 16 * 128 +
                            (((ks * 2 + cb) ^ xr) * 16);
            LDSM_X4(b[np][0], b[np][1], b[np][2], b[np][3], addr);
        }
#pragma unroll
        for (int mt = 0; mt < 4; mt++)
#pragma unroll
            for (int nt = 0; nt < 4; nt++)
                MMA_FP16(acc[mt][nt], a[mt],
                         b[nt >> 1][(nt & 1) * 2], b[nt >> 1][(nt & 1) * 2 + 1]);
    }

    float* dst = g_part + (size_t)kz * (B_DIM * O_DIM);
    const int gq = lane >> 2;
    const int tq = lane & 3;
#pragma unroll
    for (int mt = 0; mt < 4; mt++) {
#pragma unroll
        for (int nt = 0; nt < 4; nt++) {
            int row = wm * 64 + mt * 16 + gq;
            int col = bn + wn * 32 + nt * 8 + tq * 2;
            *(float2*)(dst + (size_t)row * O_DIM + col) =
                make_float2(acc[mt][nt][0], acc[mt][nt][1]);
            *(float2*)(dst + (size_t)(row + 8) * O_DIM + col) =
                make_float2(acc[mt][nt][2], acc[mt][nt][3]);
        }
    }
}

__global__ __launch_bounds__(256)
void gemm2_reduce(const float* __restrict__ bias, float* __restrict__ Y) {
    int i = blockIdx.x * 256 + threadIdx.x;          // 0..B*O-1
    float s = bias[i & (O_DIM - 1)];
#pragma unroll
    for (int z = 0; z < NSPLIT2; z++)
        s += g_part[(size_t)z * (B_DIM * O_DIM) + i];
    Y[i] = s;
}

// ---------------------------------------------------------------------------
extern "C" void kernel_launch(void* const* d_in, const int* in_sizes, int n_in,
                              void* d_out, int out_size) {
    (void)in_sizes; (void)n_in; (void)out_size;
    const float* X    = (const float*)d_in[0];   // [T,B,I]
    const float* W_IH = (const float*)d_in[1];   // [H,I]
    const float* HH   = (const float*)d_in[2];   // [H]
    const float* W_HO = (const float*)d_in[3];   // [O,H]
    const float* b_HO = (const float*)d_in[4];   // [O]
    float* Y = (float*)d_out;                    // [B,O]

    cudaFuncSetAttribute(gemm1_mma, cudaFuncAttributeMaxDynamicSharedMemorySize,
                         SMEM_DYN);
    cudaFuncSetAttribute(gemm2_mma, cudaFuncAttributeMaxDynamicSharedMemorySize,
                         G2_SMEM);

    // fp16 operand materialization (X, W_IH, W_HO in one launch)
    conv_kernel<<<NB_A + NB_B + NB_W, 256>>>(X, W_IH, W_HO);

    // proj = X @ W_IH^T, fp16 (K = 512), fp16 output
    gemm1_mma<<<dim3(H_DIM / 128, M_DIM / 128), 256, SMEM_DYN>>>();

    // sequential |.| recurrence over t -> fp16 hfinal
    recur_kernel<<<(BH / 2) / 256, 256>>>(HH);

    // Y = hfinal @ W_HO^T + b  (tensor-core, 32-way split-K + reduce)
    gemm2_mma<<<dim3(O_DIM / 128, NSPLIT2), 256, G2_SMEM>>>();
    gemm2_reduce<<<(B_DIM * O_DIM) / 256, 256>>>(b_HO, Y);
}